// round 9
// baseline (speedup 1.0000x reference)
#include <cuda_runtime.h>
#include <cuda_fp16.h>
#include <cstdint>

// ---------------- problem constants ----------------
#define B_   64
#define N_   10000
#define D_   66
#define E_   160000
#define O_   64
#define RH   4224            // halves per x row = 64*66 (unpadded)
#define RU4  528             // uint4 per x row
#define U4T  264             // uint4 per SpMM feature half (2 halves)
#define KPAD 384             // W'^T logical row length (k=m*72+d, zeros padded)
#define KS   392             // smem-padded W'^T row (bank-conflict-free)
#define NPAIR 5000
#define GEMM_GRID 296

// ---------------- scratch (slack for GEMM tail overreads) ----------------
__device__ __half g_x0h [42241024];
__device__ __half g_x1a [42241024];
__device__ __half g_ya  [42241024];
__device__ __half g_x1b [42241024];
__device__ __half g_yb  [42241024];
__device__ __half g_wt  [64 * KPAD];   // W'^T fp16, [o][k=m*72+d], zeros padded

__device__ int   g_cnt [2][N_];
__device__ int   g_rp  [2][N_ + 1];
__device__ int   g_cur [2][N_];
__device__ int   g_colS[2][E_];
__device__ float g_valS[2][E_];

// ---------------- small kernels ----------------

// W'^T fp16 [64][KPAD], logical k = m*72 + d ; folds x2 = 2*spmm(x1) - x0
__global__ void k_wt(const float* __restrict__ w, __half* __restrict__ wt) {
    int i = blockIdx.x * blockDim.x + threadIdx.x;
    if (i >= 64 * KPAD) return;
    int o = i / KPAD, k = i - o * KPAD;
    int m = k / 72, d = k - m * 72;
    float v = 0.f;
    if (m < 5 && d < D_) {
        if (m == 0)
            v = w[(d * 5 + 0) * 64 + o] - w[(d * 5 + 2) * 64 + o] - w[(d * 5 + 4) * 64 + o];
        else if (m == 2 || m == 4)
            v = 2.0f * w[(d * 5 + m) * 64 + o];
        else
            v = w[(d * 5 + m) * 64 + o];
    }
    wt[i] = __float2half_rn(v);
}

// x0h[n][b*66+d] = inputs[b][n*66+d]  (fp16, unpadded, b-major)
__global__ void k_transpose(const float* __restrict__ in, half2* __restrict__ x0h) {
    int n = blockIdx.x;
    for (int j = threadIdx.x; j < RH / 2; j += 256) {
        int i = 2 * j;
        int b = i / D_, d = i - b * D_;
        float2 v = *reinterpret_cast<const float2*>(in + (size_t)b * (N_ * D_) +
                                                    (size_t)n * D_ + d);
        x0h[(size_t)n * (RH / 2) + j] = __floats2half2_rn(v.x, v.y);
    }
}

__global__ void k_zero_int(int* __restrict__ p, int n) {
    int i = blockIdx.x * blockDim.x + threadIdx.x;
    if (i < n) p[i] = 0;
}
// both supports in one launch
__global__ void k_hist2(const int* __restrict__ rows0, const int* __restrict__ rows1,
                        int* __restrict__ cnt) {
    int e = blockIdx.x * blockDim.x + threadIdx.x;
    if (e < E_) atomicAdd(&cnt[rows0[e]], 1);
    else if (e < 2 * E_) atomicAdd(&cnt[N_ + rows1[e - E_]], 1);
}
// grid = 2 blocks, one per support
__global__ void k_scan(const int* __restrict__ cnt_all, int* __restrict__ rp_all,
                       int* __restrict__ cur_all) {
    __shared__ int part[1024];
    const int CH = 10;
    const int s = blockIdx.x;
    const int* cnt = cnt_all + s * N_;
    int* rowptr = rp_all + s * (N_ + 1);
    int* cursor = cur_all + s * N_;
    int t = threadIdx.x;
    int base = t * CH;
    int loc[CH];
    int acc = 0;
#pragma unroll
    for (int j = 0; j < CH; j++) {
        int i = base + j;
        int c = (i < N_) ? cnt[i] : 0;
        loc[j] = c;
        acc += c;
    }
    part[t] = acc;
    __syncthreads();
    for (int off = 1; off < 1024; off <<= 1) {
        int v = (t >= off) ? part[t - off] : 0;
        __syncthreads();
        part[t] += v;
        __syncthreads();
    }
    int off0 = (t > 0) ? part[t - 1] : 0;
#pragma unroll
    for (int j = 0; j < CH; j++) {
        int i = base + j;
        if (i < N_) {
            rowptr[i] = off0;
            cursor[i] = off0;
            off0 += loc[j];
        }
    }
    if (t == 1023) rowptr[N_] = part[1023];
}
__global__ void k_scatter2(const int* __restrict__ rows0, const int* __restrict__ cols0,
                           const float* __restrict__ vals0,
                           const int* __restrict__ rows1, const int* __restrict__ cols1,
                           const float* __restrict__ vals1,
                           int* __restrict__ cur_all, int* __restrict__ colS_all,
                           float* __restrict__ valS_all) {
    int e = blockIdx.x * blockDim.x + threadIdx.x;
    if (e < E_) {
        int r = rows0[e];
        int p = atomicAdd(&cur_all[r], 1);
        colS_all[p] = cols0[e];
        valS_all[p] = vals0[e];
    } else if (e < 2 * E_) {
        int ee = e - E_;
        int r = rows1[ee];
        int p = atomicAdd(&cur_all[N_ + r], 1);
        colS_all[E_ + p] = cols1[ee];
        valS_all[E_ + p] = vals1[ee];
    }
}

// CSR SpMM, one feature half per launch (keeps 42MB R + 42MB W inside L2).
// block = row; 288 threads, 264 active gather lanes of uint4 (8 halves each).
__global__ void __launch_bounds__(288) k_spmm_h(
    const int* __restrict__ rowptr, const int* __restrict__ colS,
    const float* __restrict__ valS, const uint4* __restrict__ xh,
    uint4* __restrict__ yh, int half) {
    __shared__ int   sc[288];
    __shared__ float sv[288];
    int r = blockIdx.x;
    int t = threadIdx.x;
    int i4 = half * U4T + t;
    bool act = (t < U4T);
    int e0 = rowptr[r], e1 = rowptr[r + 1];

    float a0 = 0.f, a1 = 0.f, a2 = 0.f, a3 = 0.f;
    float a4 = 0.f, a5 = 0.f, a6 = 0.f, a7 = 0.f;

    for (int es = e0; es < e1; es += 288) {
        int ne = min(288, e1 - es);
        if (t < ne) { sc[t] = colS[es + t]; sv[t] = valS[es + t]; }
        __syncthreads();
        if (act) {
#pragma unroll 4
            for (int j = 0; j < ne; j++) {
                int c = sc[j];
                float v = sv[j];
                uint4 p = __ldg(xh + (size_t)c * RU4 + i4);
                float2 f0 = __half22float2(*reinterpret_cast<half2*>(&p.x));
                float2 f1 = __half22float2(*reinterpret_cast<half2*>(&p.y));
                float2 f2 = __half22float2(*reinterpret_cast<half2*>(&p.z));
                float2 f3 = __half22float2(*reinterpret_cast<half2*>(&p.w));
                a0 += v * f0.x; a1 += v * f0.y;
                a2 += v * f1.x; a3 += v * f1.y;
                a4 += v * f2.x; a5 += v * f2.y;
                a6 += v * f3.x; a7 += v * f3.y;
            }
        }
        __syncthreads();
    }
    if (act) {
        half2 h0 = __floats2half2_rn(a0, a1);
        half2 h1 = __floats2half2_rn(a2, a3);
        half2 h2 = __floats2half2_rn(a4, a5);
        half2 h3 = __floats2half2_rn(a6, a7);
        uint4 o;
        o.x = *reinterpret_cast<unsigned*>(&h0);
        o.y = *reinterpret_cast<unsigned*>(&h1);
        o.z = *reinterpret_cast<unsigned*>(&h2);
        o.w = *reinterpret_cast<unsigned*>(&h3);
        yh[(size_t)r * RU4 + i4] = o;
    }
}

// ---------------- HMMA GEMM (mma.sync m16n8k16) ----------------
// Logical k = m*72+d lives in B (zeros at d>=66); A is unpadded (stride 66).
// Every 8-half fragment is within one m (72 % 8 == 0), so m, d are compile-time.
// Fragment halves with d in [66,72) read garbage but hit zero B columns.
__global__ void __launch_bounds__(256, 2) k_gemm_mma(
    const __half* __restrict__ x0, const __half* __restrict__ x1a,
    const __half* __restrict__ ya, const __half* __restrict__ x1b,
    const __half* __restrict__ yb, const __half* __restrict__ wt,
    const float* __restrict__ bias, float* __restrict__ out) {
    extern __shared__ __half sB[];   // [64][KS]
    int t = threadIdx.x, wid = t >> 5, lane = t & 31;
    int g = lane >> 2, tid4 = lane & 3;

    const uint4* wt4 = reinterpret_cast<const uint4*>(wt);
    for (int i = t; i < 3072; i += 256) {
        int r = i / 48, c = i - r * 48;
        *reinterpret_cast<uint4*>(sB + r * KS + c * 8) = wt4[i];
    }
    __syncthreads();

    int p = wid >> 2;               // node within pair
    int b_lo = (wid & 3) * 16 + g;  // batch row (lo); hi = +8
    const __half* xs[5] = {x0, x1a, ya, x1b, yb};

    for (int tile = blockIdx.x; tile < NPAIR; tile += gridDim.x) {
        int n = tile * 2 + p;
        size_t baseL = (size_t)n * RH + (size_t)b_lo * D_ + tid4 * 2;
        size_t baseH = baseL + 8 * D_;

        float acc[8][4];
#pragma unroll
        for (int ng = 0; ng < 8; ng++)
#pragma unroll
            for (int q = 0; q < 4; q++) acc[ng][q] = 0.f;

#pragma unroll
        for (int ks = 0; ks < 23; ks++) {
            const int klo = ks * 16;
            const int khi = klo + 8;
            const int mlo = klo / 72, dlo = klo - mlo * 72;
            const int mhi = khi / 72, dhi = khi - mhi * 72;
            unsigned a0, a1, a2, a3;
            a0 = *reinterpret_cast<const unsigned*>(xs[mlo] + baseL + dlo);
            a1 = *reinterpret_cast<const unsigned*>(xs[mlo] + baseH + dlo);
            if (mhi < 5) {
                a2 = *reinterpret_cast<const unsigned*>(xs[mhi] + baseL + dhi);
                a3 = *reinterpret_cast<const unsigned*>(xs[mhi] + baseH + dhi);
            } else {
                a2 = 0u; a3 = 0u;
            }
#pragma unroll
            for (int ng = 0; ng < 8; ng++) {
                const __half* bp = sB + (ng * 8 + g) * KS + klo + tid4 * 2;
                unsigned b0 = *reinterpret_cast<const unsigned*>(bp);
                unsigned b1 = *reinterpret_cast<const unsigned*>(bp + 8);
                asm volatile(
                    "mma.sync.aligned.m16n8k16.row.col.f32.f16.f16.f32 "
                    "{%0,%1,%2,%3}, {%4,%5,%6,%7}, {%8,%9}, {%0,%1,%2,%3};"
                    : "+f"(acc[ng][0]), "+f"(acc[ng][1]),
                      "+f"(acc[ng][2]), "+f"(acc[ng][3])
                    : "r"(a0), "r"(a1), "r"(a2), "r"(a3), "r"(b0), "r"(b1));
            }
        }

        float* orow_lo = out + (size_t)b_lo * ((size_t)N_ * O_) + (size_t)n * O_;
        float* orow_hi = orow_lo + 8 * ((size_t)N_ * O_);
#pragma unroll
        for (int ng = 0; ng < 8; ng++) {
            int col = ng * 8 + tid4 * 2;
            float2 bv = __ldg(reinterpret_cast<const float2*>(bias + col));
            float2 vlo = make_float2(acc[ng][0] + bv.x, acc[ng][1] + bv.y);
            float2 vhi = make_float2(acc[ng][2] + bv.x, acc[ng][3] + bv.y);
            *reinterpret_cast<float2*>(orow_lo + col) = vlo;
            *reinterpret_cast<float2*>(orow_hi + col) = vhi;
        }
    }
}

// ---------------- launch ----------------
extern "C" void kernel_launch(void* const* d_in, const int* in_sizes, int n_in,
                              void* d_out, int out_size) {
    const float* inputs = (const float*)d_in[0];
    const float* weight = (const float*)d_in[2];
    const float* biases = (const float*)d_in[3];
    const float* vals0  = (const float*)d_in[4];
    const float* vals1  = (const float*)d_in[5];
    const int*   rows0  = (const int*)d_in[6];
    const int*   cols0  = (const int*)d_in[7];
    const int*   rows1  = (const int*)d_in[8];
    const int*   cols1  = (const int*)d_in[9];
    float* out = (float*)d_out;

    __half *x0h, *x1a, *ya, *x1b, *yb, *wt;
    float* valS;
    int *cnt, *rp, *cur, *colS;
    cudaGetSymbolAddress((void**)&x0h, g_x0h);
    cudaGetSymbolAddress((void**)&x1a, g_x1a);
    cudaGetSymbolAddress((void**)&ya,  g_ya);
    cudaGetSymbolAddress((void**)&x1b, g_x1b);
    cudaGetSymbolAddress((void**)&yb,  g_yb);
    cudaGetSymbolAddress((void**)&wt,  g_wt);
    cudaGetSymbolAddress((void**)&cnt,  g_cnt);
    cudaGetSymbolAddress((void**)&rp,   g_rp);
    cudaGetSymbolAddress((void**)&cur,  g_cur);
    cudaGetSymbolAddress((void**)&colS, g_colS);
    cudaGetSymbolAddress((void**)&valS, g_valS);

    // CSR prep + transpose first (launches 1-5) so ncu -s 5 lands on SpMM
    k_zero_int<<<(2 * N_ + 255) / 256, 256>>>(cnt, 2 * N_);
    k_hist2<<<(2 * E_ + 255) / 256, 256>>>(rows0, rows1, cnt);
    k_scan<<<2, 1024>>>(cnt, rp, cur);
    k_scatter2<<<(2 * E_ + 255) / 256, 256>>>(rows0, cols0, vals0,
                                              rows1, cols1, vals1,
                                              cur, colS, valS);
    k_transpose<<<N_, 256>>>(inputs, (half2*)x0h);

    int* rp0 = rp;
    int* rp1 = rp + (N_ + 1);
    int* colS0 = colS;
    int* colS1 = colS + E_;
    float* valS0 = valS;
    float* valS1 = valS + E_;

    // feature-phased SpMM: per half, chain a1 -> b1 -> a2 -> b2 (L2-resident)
    for (int h = 0; h < 2; h++) {
        k_spmm_h<<<N_, 288>>>(rp0, colS0, valS0, (const uint4*)x0h, (uint4*)x1a, h);
        k_spmm_h<<<N_, 288>>>(rp1, colS1, valS1, (const uint4*)x0h, (uint4*)x1b, h);
        k_spmm_h<<<N_, 288>>>(rp0, colS0, valS0, (const uint4*)x1a, (uint4*)ya, h);
        k_spmm_h<<<N_, 288>>>(rp1, colS1, valS1, (const uint4*)x1b, (uint4*)yb, h);
    }

    k_wt<<<(64 * KPAD + 255) / 256, 256>>>(weight, wt);

    const int smem_gemm = 64 * KS * 2;  // 50176 B
    cudaFuncSetAttribute(k_gemm_mma, cudaFuncAttributeMaxDynamicSharedMemorySize, smem_gemm);
    k_gemm_mma<<<GEMM_GRID, 256, smem_gemm>>>(x0h, x1a, ya, x1b, yb, wt, biases, out);
}

// round 10
// speedup vs baseline: 1.1386x; 1.1386x over previous
#include <cuda_runtime.h>
#include <cuda_fp16.h>
#include <cstdint>

// ---------------- problem constants ----------------
#define B_   64
#define N_   10000
#define D_   66
#define E_   160000
#define O_   64
#define RH   4224            // halves per x row = 64*66 (unpadded)
#define RU4  528             // uint4 per x row
#define U4T  264             // uint4 per SpMM feature tile (2 tiles)
#define KPAD 384             // W'^T logical row length (k=m*72+d, zeros padded)
#define KS   392             // smem-padded W'^T row (bank-conflict-free)
#define NPAIR 5000
#define GEMM_GRID 296

// ---------------- scratch (slack for GEMM tail overreads) ----------------
__device__ __half g_x0h [42241024];
__device__ __half g_x1a [42241024];
__device__ __half g_ya  [42241024];
__device__ __half g_x1b [42241024];
__device__ __half g_yb  [42241024];
__device__ __half g_wt  [64 * KPAD];   // W'^T fp16, [o][k=m*72+d], zeros padded

__device__ int   g_cnt [2][N_];        // zero-on-entry invariant (re-zeroed by GEMM)
__device__ int   g_rp  [2][N_ + 1];
__device__ int   g_cur [2][N_];
__device__ int   g_colS[2][E_];
__device__ float g_valS[2][E_];

// ---------------- kernels ----------------

// launch 1: histogram both supports (cnt must be zero on entry; invariant)
__global__ void k_hist2(const int* __restrict__ rows0, const int* __restrict__ rows1,
                        int* __restrict__ cnt) {
    int e = blockIdx.x * blockDim.x + threadIdx.x;
    if (e < E_) atomicAdd(&cnt[rows0[e]], 1);
    else if (e < 2 * E_) atomicAdd(&cnt[N_ + rows1[e - E_]], 1);
}

// launch 2: grid = 2 blocks, one per support
__global__ void k_scan(const int* __restrict__ cnt_all, int* __restrict__ rp_all,
                       int* __restrict__ cur_all) {
    __shared__ int part[1024];
    const int CH = 10;
    const int s = blockIdx.x;
    const int* cnt = cnt_all + s * N_;
    int* rowptr = rp_all + s * (N_ + 1);
    int* cursor = cur_all + s * N_;
    int t = threadIdx.x;
    int base = t * CH;
    int loc[CH];
    int acc = 0;
#pragma unroll
    for (int j = 0; j < CH; j++) {
        int i = base + j;
        int c = (i < N_) ? cnt[i] : 0;
        loc[j] = c;
        acc += c;
    }
    part[t] = acc;
    __syncthreads();
    for (int off = 1; off < 1024; off <<= 1) {
        int v = (t >= off) ? part[t - off] : 0;
        __syncthreads();
        part[t] += v;
        __syncthreads();
    }
    int off0 = (t > 0) ? part[t - 1] : 0;
#pragma unroll
    for (int j = 0; j < CH; j++) {
        int i = base + j;
        if (i < N_) {
            rowptr[i] = off0;
            cursor[i] = off0;
            off0 += loc[j];
        }
    }
    if (t == 1023) rowptr[N_] = part[1023];
}

// launch 3: fused scatter (blocks 0..1249) + transpose (blocks 1250..11249)
//           + W' build (blocks 11250..11345)
__global__ void __launch_bounds__(256) k_fuse(
    const int* __restrict__ rows0, const int* __restrict__ cols0,
    const float* __restrict__ vals0,
    const int* __restrict__ rows1, const int* __restrict__ cols1,
    const float* __restrict__ vals1,
    int* __restrict__ cur_all, int* __restrict__ colS_all, float* __restrict__ valS_all,
    const float* __restrict__ in, half2* __restrict__ x0h,
    const float* __restrict__ w, __half* __restrict__ wt) {
    int bx = blockIdx.x;
    if (bx < 1250) {
        int e = bx * 256 + threadIdx.x;
        if (e < E_) {
            int r = rows0[e];
            int p = atomicAdd(&cur_all[r], 1);
            colS_all[p] = cols0[e];
            valS_all[p] = vals0[e];
        } else if (e < 2 * E_) {
            int ee = e - E_;
            int r = rows1[ee];
            int p = atomicAdd(&cur_all[N_ + r], 1);
            colS_all[E_ + p] = cols1[ee];
            valS_all[E_ + p] = vals1[ee];
        }
    } else if (bx < 11250) {
        int n = bx - 1250;
        for (int j = threadIdx.x; j < RH / 2; j += 256) {
            int i = 2 * j;
            int b = i / D_, d = i - b * D_;
            float2 v = *reinterpret_cast<const float2*>(in + (size_t)b * (N_ * D_) +
                                                        (size_t)n * D_ + d);
            x0h[(size_t)n * (RH / 2) + j] = __floats2half2_rn(v.x, v.y);
        }
    } else {
        int i = (bx - 11250) * 256 + threadIdx.x;
        if (i < 64 * KPAD) {
            int o = i / KPAD, k = i - o * KPAD;
            int m = k / 72, d = k - m * 72;
            float v = 0.f;
            if (m < 5 && d < D_) {
                if (m == 0)
                    v = w[(d * 5 + 0) * 64 + o] - w[(d * 5 + 2) * 64 + o] -
                        w[(d * 5 + 4) * 64 + o];
                else if (m == 2 || m == 4)
                    v = 2.0f * w[(d * 5 + m) * 64 + o];
                else
                    v = w[(d * 5 + m) * 64 + o];
            }
            wt[i] = __float2half_rn(v);
        }
    }
}

// launches 4-7: CSR SpMM, fp16 gather / fp32 accum / fp16 out.
// block = (row, feature tile of 264 u4); 288 threads, 264 active.
__global__ void __launch_bounds__(288) k_spmm_h(
    const int* __restrict__ rowptr, const int* __restrict__ colS,
    const float* __restrict__ valS, const uint4* __restrict__ xh,
    uint4* __restrict__ yh) {
    __shared__ int   sc[288];
    __shared__ float sv[288];
    int r = blockIdx.x;
    int t = threadIdx.x;
    int i4 = blockIdx.y * U4T + t;
    bool act = (t < U4T);
    int e0 = __ldg(rowptr + r), e1 = __ldg(rowptr + r + 1);

    float a0 = 0.f, a1 = 0.f, a2 = 0.f, a3 = 0.f;
    float a4 = 0.f, a5 = 0.f, a6 = 0.f, a7 = 0.f;

    for (int es = e0; es < e1; es += 288) {
        if (es != e0) __syncthreads();      // protect re-staging only
        int ne = min(288, e1 - es);
        if (t < ne) { sc[t] = colS[es + t]; sv[t] = valS[es + t]; }
        __syncthreads();
        if (act) {
#pragma unroll 4
            for (int j = 0; j < ne; j++) {
                int c = sc[j];
                float v = sv[j];
                uint4 p = __ldg(xh + (size_t)c * RU4 + i4);
                float2 f0 = __half22float2(*reinterpret_cast<half2*>(&p.x));
                float2 f1 = __half22float2(*reinterpret_cast<half2*>(&p.y));
                float2 f2 = __half22float2(*reinterpret_cast<half2*>(&p.z));
                float2 f3 = __half22float2(*reinterpret_cast<half2*>(&p.w));
                a0 += v * f0.x; a1 += v * f0.y;
                a2 += v * f1.x; a3 += v * f1.y;
                a4 += v * f2.x; a5 += v * f2.y;
                a6 += v * f3.x; a7 += v * f3.y;
            }
        }
    }
    if (act) {
        half2 h0 = __floats2half2_rn(a0, a1);
        half2 h1 = __floats2half2_rn(a2, a3);
        half2 h2 = __floats2half2_rn(a4, a5);
        half2 h3 = __floats2half2_rn(a6, a7);
        uint4 o;
        o.x = *reinterpret_cast<unsigned*>(&h0);
        o.y = *reinterpret_cast<unsigned*>(&h1);
        o.z = *reinterpret_cast<unsigned*>(&h2);
        o.w = *reinterpret_cast<unsigned*>(&h3);
        yh[(size_t)r * RU4 + i4] = o;
    }
}

// launch 8: HMMA GEMM (mma.sync m16n8k16). Also restores cnt=0 invariant.
// Logical k = m*72+d lives in B (zeros at d>=66); A is unpadded (stride 66).
__global__ void __launch_bounds__(256, 2) k_gemm_mma(
    const __half* __restrict__ x0, const __half* __restrict__ x1a,
    const __half* __restrict__ ya, const __half* __restrict__ x1b,
    const __half* __restrict__ yb, const __half* __restrict__ wt,
    const float* __restrict__ bias, float* __restrict__ out,
    int* __restrict__ cnt) {
    extern __shared__ __half sB[];   // [64][KS]
    int t = threadIdx.x, wid = t >> 5, lane = t & 31;
    int g = lane >> 2, tid4 = lane & 3;

    // restore cnt = 0 for the next call (cnt is dead after k_scan)
    int zi = blockIdx.x * 256 + t;
    if (zi < 2 * N_) cnt[zi] = 0;

    const uint4* wt4 = reinterpret_cast<const uint4*>(wt);
    for (int i = t; i < 3072; i += 256) {
        int r = i / 48, c = i - r * 48;
        *reinterpret_cast<uint4*>(sB + r * KS + c * 8) = wt4[i];
    }
    __syncthreads();

    int p = wid >> 2;               // node within pair
    int b_lo = (wid & 3) * 16 + g;  // batch row (lo); hi = +8
    const __half* xs[5] = {x0, x1a, ya, x1b, yb};

    for (int tile = blockIdx.x; tile < NPAIR; tile += gridDim.x) {
        int n = tile * 2 + p;
        size_t baseL = (size_t)n * RH + (size_t)b_lo * D_ + tid4 * 2;
        size_t baseH = baseL + 8 * D_;

        float acc[8][4];
#pragma unroll
        for (int ng = 0; ng < 8; ng++)
#pragma unroll
            for (int q = 0; q < 4; q++) acc[ng][q] = 0.f;

#pragma unroll
        for (int ks = 0; ks < 23; ks++) {
            const int klo = ks * 16;
            const int khi = klo + 8;
            const int mlo = klo / 72, dlo = klo - mlo * 72;
            const int mhi = khi / 72, dhi = khi - mhi * 72;
            unsigned a0, a1, a2, a3;
            a0 = *reinterpret_cast<const unsigned*>(xs[mlo] + baseL + dlo);
            a1 = *reinterpret_cast<const unsigned*>(xs[mlo] + baseH + dlo);
            if (mhi < 5) {
                a2 = *reinterpret_cast<const unsigned*>(xs[mhi] + baseL + dhi);
                a3 = *reinterpret_cast<const unsigned*>(xs[mhi] + baseH + dhi);
            } else {
                a2 = 0u; a3 = 0u;
            }
#pragma unroll
            for (int ng = 0; ng < 8; ng++) {
                const __half* bp = sB + (ng * 8 + g) * KS + klo + tid4 * 2;
                unsigned b0 = *reinterpret_cast<const unsigned*>(bp);
                unsigned b1 = *reinterpret_cast<const unsigned*>(bp + 8);
                asm volatile(
                    "mma.sync.aligned.m16n8k16.row.col.f32.f16.f16.f32 "
                    "{%0,%1,%2,%3}, {%4,%5,%6,%7}, {%8,%9}, {%0,%1,%2,%3};"
                    : "+f"(acc[ng][0]), "+f"(acc[ng][1]),
                      "+f"(acc[ng][2]), "+f"(acc[ng][3])
                    : "r"(a0), "r"(a1), "r"(a2), "r"(a3), "r"(b0), "r"(b1));
            }
        }

        float* orow_lo = out + (size_t)b_lo * ((size_t)N_ * O_) + (size_t)n * O_;
        float* orow_hi = orow_lo + 8 * ((size_t)N_ * O_);
#pragma unroll
        for (int ng = 0; ng < 8; ng++) {
            int col = ng * 8 + tid4 * 2;
            float2 bv = __ldg(reinterpret_cast<const float2*>(bias + col));
            float2 vlo = make_float2(acc[ng][0] + bv.x, acc[ng][1] + bv.y);
            float2 vhi = make_float2(acc[ng][2] + bv.x, acc[ng][3] + bv.y);
            *reinterpret_cast<float2*>(orow_lo + col) = vlo;
            *reinterpret_cast<float2*>(orow_hi + col) = vhi;
        }
    }
}

// ---------------- launch ----------------
extern "C" void kernel_launch(void* const* d_in, const int* in_sizes, int n_in,
                              void* d_out, int out_size) {
    const float* inputs = (const float*)d_in[0];
    const float* weight = (const float*)d_in[2];
    const float* biases = (const float*)d_in[3];
    const float* vals0  = (const float*)d_in[4];
    const float* vals1  = (const float*)d_in[5];
    const int*   rows0  = (const int*)d_in[6];
    const int*   cols0  = (const int*)d_in[7];
    const int*   rows1  = (const int*)d_in[8];
    const int*   cols1  = (const int*)d_in[9];
    float* out = (float*)d_out;

    __half *x0h, *x1a, *ya, *x1b, *yb, *wt;
    float* valS;
    int *cnt, *rp, *cur, *colS;
    cudaGetSymbolAddress((void**)&x0h, g_x0h);
    cudaGetSymbolAddress((void**)&x1a, g_x1a);
    cudaGetSymbolAddress((void**)&ya,  g_ya);
    cudaGetSymbolAddress((void**)&x1b, g_x1b);
    cudaGetSymbolAddress((void**)&yb,  g_yb);
    cudaGetSymbolAddress((void**)&wt,  g_wt);
    cudaGetSymbolAddress((void**)&cnt,  g_cnt);
    cudaGetSymbolAddress((void**)&rp,   g_rp);
    cudaGetSymbolAddress((void**)&cur,  g_cur);
    cudaGetSymbolAddress((void**)&colS, g_colS);
    cudaGetSymbolAddress((void**)&valS, g_valS);

    // 1: histogram (cnt zero-on-entry invariant)
    k_hist2<<<(2 * E_ + 255) / 256, 256>>>(rows0, rows1, cnt);
    // 2: scan
    k_scan<<<2, 1024>>>(cnt, rp, cur);
    // 3: fused scatter + transpose + W' build
    k_fuse<<<11250 + (64 * KPAD + 255) / 256, 256>>>(
        rows0, cols0, vals0, rows1, cols1, vals1, cur, colS, valS,
        inputs, (half2*)x0h, weight, wt);

    int* rp0 = rp;
    int* rp1 = rp + (N_ + 1);
    int* colS0 = colS;
    int* colS1 = colS + E_;
    float* valS0 = valS;
    float* valS1 = valS + E_;

    // 4-7: SpMM (2D grid; stage-1 pair first so x0 stays hot)
    dim3 gs(N_, 2);
    k_spmm_h<<<gs, 288>>>(rp0, colS0, valS0, (const uint4*)x0h, (uint4*)x1a);
    k_spmm_h<<<gs, 288>>>(rp1, colS1, valS1, (const uint4*)x0h, (uint4*)x1b);
    k_spmm_h<<<gs, 288>>>(rp0, colS0, valS0, (const uint4*)x1a, (uint4*)ya);
    k_spmm_h<<<gs, 288>>>(rp1, colS1, valS1, (const uint4*)x1b, (uint4*)yb);

    // 8: GEMM (+ cnt re-zero)
    const int smem_gemm = 64 * KS * 2;  // 50176 B
    cudaFuncSetAttribute(k_gemm_mma, cudaFuncAttributeMaxDynamicSharedMemorySize, smem_gemm);
    k_gemm_mma<<<GEMM_GRID, 256, smem_gemm>>>(x0h, x1a, ya, x1b, yb, wt, biases, out, cnt);
}